// round 2
// baseline (speedup 1.0000x reference)
#include <cuda_runtime.h>
#include <cuda_bf16.h>
#include <cstdint>

#define B_    16
#define N_    64
#define C_    128
#define H_    64
#define W_    64
#define HW_   (H_ * W_)           // 4096
#define OUT_  256
#define NROI  (B_ * N_)           // 1024
#define SCALE 0.125f
#define MAXG  16

// ---------------- scratch (no allocations allowed) ----------------
__device__ float g_zf[B_ * HW_ * C_];      // [B,H,W,C]  32 MB
__device__ float g_feats[NROI * C_];       // [1024,128] 512 KB

// ---------------- kernel 1: NCHW -> NHWC transpose ----------------
// per batch: [C=128, HW=4096] -> [HW, C]. 32x32 smem tiles, coalesced both ways.
__global__ void transpose_kernel(const float* __restrict__ z, float* __restrict__ zf) {
    __shared__ float tile[32][33];
    const int b  = blockIdx.z;
    const int p0 = blockIdx.x * 32;   // spatial
    const int c0 = blockIdx.y * 32;   // channel
    const int tx = threadIdx.x, ty = threadIdx.y;

    const float* src = z  + (size_t)b * C_ * HW_;
    float*       dst = zf + (size_t)b * HW_ * C_;

#pragma unroll
    for (int i = 0; i < 32; i += 8)
        tile[ty + i][tx] = src[(size_t)(c0 + ty + i) * HW_ + (p0 + tx)];
    __syncthreads();
#pragma unroll
    for (int i = 0; i < 32; i += 8)
        dst[(size_t)(p0 + ty + i) * C_ + (c0 + tx)] = tile[tx][ty + i];
}

// ---------------- kernel 2: roi_align 1x1 (adaptive grid) ----------------
// warp = one ROI, lane = 4 channels (float4). 4 warps per block.
#define ROIS_PER_BLK 4
__global__ void __launch_bounds__(32 * ROIS_PER_BLK) roi_align_kernel(
    const float* __restrict__ zf,
    const float* __restrict__ bboxes,
    float* __restrict__ feats)
{
    const int warp = threadIdx.x >> 5;
    const int lane = threadIdx.x & 31;
    const int roi  = blockIdx.x * ROIS_PER_BLK + warp;   // b*N + n
    const int b    = roi >> 6;                           // N=64

    const float4 box = __ldg(reinterpret_cast<const float4*>(bboxes) + roi);
    const float x1 = box.x * SCALE - 0.5f;
    const float y1 = box.y * SCALE - 0.5f;
    const float x2 = box.z * SCALE - 0.5f;
    const float y2 = box.w * SCALE - 0.5f;
    const float rw = x2 - x1, rh = y2 - y1;
    const float gw = fminf(fmaxf(ceilf(rw), 1.f), (float)MAXG);
    const float gh = fminf(fmaxf(ceilf(rh), 1.f), (float)MAXG);
    const int igw = (int)gw, igh = (int)gh;
    const float bwx = rw / gw, bwy = rh / gh;

    // per-warp coordinate tables
    __shared__ int   s_xl[ROIS_PER_BLK][MAXG], s_xh[ROIS_PER_BLK][MAXG];
    __shared__ int   s_yl[ROIS_PER_BLK][MAXG], s_yh[ROIS_PER_BLK][MAXG];
    __shared__ float s_fx[ROIS_PER_BLK][MAXG], s_fy[ROIS_PER_BLK][MAXG];
    __shared__ float s_mx[ROIS_PER_BLK][MAXG], s_my[ROIS_PER_BLK][MAXG];

    // lanes 0-15: x coords; lanes 16-31: y coords (torchvision _prep_coord)
    {
        const int g   = lane & 15;
        const bool isx = lane < 16;
        const float o  = isx ? x1  : y1;
        const float bw = isx ? bwx : bwy;
        const float L  = isx ? (float)W_ : (float)H_;   // W_ == H_ but keep general
        float cc0 = o + ((float)g + 0.5f) * bw;
        float inr = (cc0 > -1.0f && cc0 < L) ? 1.0f : 0.0f;
        float cc = fmaxf(cc0, 0.0f);
        int lo = min((int)floorf(cc), (int)L - 1);
        int hi = min(lo + 1, (int)L - 1);
        if (lo >= (int)L - 1) cc = (float)lo;
        float fr = cc - (float)lo;
        if (isx) { s_xl[warp][g] = lo; s_xh[warp][g] = hi; s_fx[warp][g] = fr; s_mx[warp][g] = inr; }
        else     { s_yl[warp][g] = lo; s_yh[warp][g] = hi; s_fy[warp][g] = fr; s_my[warp][g] = inr; }
    }
    __syncwarp();

    const float4* zb = reinterpret_cast<const float4*>(zf + (size_t)b * HW_ * C_);
    float4 acc = make_float4(0.f, 0.f, 0.f, 0.f);

    for (int gy = 0; gy < igh; gy++) {
        const float fy = s_fy[warp][gy], hy = 1.0f - fy;
        const float my = s_my[warp][gy];
        const float4* r0 = zb + (size_t)s_yl[warp][gy] * W_ * (C_ / 4) + lane;
        const float4* r1 = zb + (size_t)s_yh[warp][gy] * W_ * (C_ / 4) + lane;
#pragma unroll 4
        for (int gx = 0; gx < igw; gx++) {
            const float fx = s_fx[warp][gx], hx = 1.0f - fx;
            const float m   = my * s_mx[warp][gx];
            const float w11 = m * hy * hx, w12 = m * hy * fx;
            const float w21 = m * fy * hx, w22 = m * fy * fx;
            const int xl = s_xl[warp][gx] * (C_ / 4);
            const int xh = s_xh[warp][gx] * (C_ / 4);
            float4 a = __ldg(r0 + xl);
            float4 bq = __ldg(r0 + xh);
            float4 cq = __ldg(r1 + xl);
            float4 d = __ldg(r1 + xh);
            acc.x += w11 * a.x + w12 * bq.x + w21 * cq.x + w22 * d.x;
            acc.y += w11 * a.y + w12 * bq.y + w21 * cq.y + w22 * d.y;
            acc.z += w11 * a.z + w12 * bq.z + w21 * cq.z + w22 * d.z;
            acc.w += w11 * a.w + w12 * bq.w + w21 * cq.w + w22 * d.w;
        }
    }
    const float inv = 1.0f / (gw * gh);
    acc.x *= inv; acc.y *= inv; acc.z *= inv; acc.w *= inv;
    reinterpret_cast<float4*>(feats)[roi * (C_ / 4) + lane] = acc;
}

// ---------------- kernel 3: feats[1024,128] @ W^T[128,256] + b ----------------
// 16 ROIs per block, 256 threads (one output channel each).
#define ROIS_PB 16
__global__ void __launch_bounds__(OUT_) gemm_kernel(
    const float* __restrict__ feats,
    const float* __restrict__ Wm,      // [256,128]
    const float* __restrict__ bias,    // [256]
    float* __restrict__ out)           // [1024,256]
{
    __shared__ float fs[ROIS_PB][C_];
    const int r0  = blockIdx.x * ROIS_PB;
    const int tid = threadIdx.x;

    // vectorized smem fill: 16*128 floats = 512 float4s, 256 threads -> 2 iters
    const float4* fsrc = reinterpret_cast<const float4*>(feats + (size_t)r0 * C_);
#pragma unroll
    for (int i = 0; i < 2; i++) {
        int idx = tid + i * OUT_;                 // float4 index in [0,512)
        float4 v = fsrc[idx];
        reinterpret_cast<float4*>(&fs[0][0])[idx] = v;
    }
    __syncthreads();

    const int oc = tid;
    const float bv = bias[oc];
    float acc[ROIS_PB];
#pragma unroll
    for (int r = 0; r < ROIS_PB; r++) acc[r] = bv;

    const float4* wrow = reinterpret_cast<const float4*>(Wm + (size_t)oc * C_);
#pragma unroll 4
    for (int c4 = 0; c4 < C_ / 4; c4 += 2) {
        float4 w0 = wrow[c4], w1 = wrow[c4 + 1];
#pragma unroll
        for (int r = 0; r < ROIS_PB; r++) {
            const float* f = &fs[r][c4 * 4];
            float s = w0.x * f[0] + w0.y * f[1] + w0.z * f[2] + w0.w * f[3]
                    + w1.x * f[4] + w1.y * f[5] + w1.z * f[6] + w1.w * f[7];
            acc[r] += s;
        }
    }
#pragma unroll
    for (int r = 0; r < ROIS_PB; r++)
        out[(size_t)(r0 + r) * OUT_ + oc] = acc[r];
}

// ---------------- launch ----------------
extern "C" void kernel_launch(void* const* d_in, const int* in_sizes, int n_in,
                              void* d_out, int out_size) {
    const float* z      = (const float*)d_in[0];  // [16,128,64,64]
    const float* bboxes = (const float*)d_in[1];  // [16,64,4]
    const float* Wm     = (const float*)d_in[2];  // [256,128]
    const float* bias   = (const float*)d_in[3];  // [256]
    float* out = (float*)d_out;                   // [16,64,256]

    float* zf;    cudaGetSymbolAddress((void**)&zf,    g_zf);
    float* feats; cudaGetSymbolAddress((void**)&feats, g_feats);

    dim3 tgrid(HW_ / 32, C_ / 32, B_);
    transpose_kernel<<<tgrid, dim3(32, 8)>>>(z, zf);

    roi_align_kernel<<<NROI / ROIS_PER_BLK, 32 * ROIS_PER_BLK>>>(zf, bboxes, feats);

    gemm_kernel<<<NROI / ROIS_PB, OUT_>>>(feats, Wm, bias, out);
}

// round 3
// speedup vs baseline: 1.5725x; 1.5725x over previous
#include <cuda_runtime.h>
#include <cuda_bf16.h>
#include <cstdint>

#define B_    16
#define N_    64
#define C_    128
#define H_    64
#define W_    64
#define HW_   (H_ * W_)           // 4096
#define OUT_  256
#define NROI  (B_ * N_)           // 1024
#define SCALE 0.125f
#define MAXG  16

// ---------------- scratch (no allocations allowed) ----------------
__device__ float g_zf[B_ * HW_ * C_];      // [B,H,W,C]  32 MB
__device__ float g_feats[NROI * C_];       // [1024,128] 512 KB

// ---------------- kernel 1: NCHW -> NHWC transpose (float4 both ways) --------
// tile: 32 channels x 32 spatial. 256 threads, each moves 4 floats vectorized.
__global__ void __launch_bounds__(256) transpose_kernel(
    const float* __restrict__ z, float* __restrict__ zf)
{
    __shared__ float tile[32][33];            // [spatial][channel]
    const int b  = blockIdx.z;
    const int p0 = blockIdx.x * 32;           // spatial base
    const int c0 = blockIdx.y * 32;           // channel base
    const int t  = threadIdx.x;

    const float* src = z  + (size_t)b * C_ * HW_;
    float*       dst = zf + (size_t)b * HW_ * C_;

    // load: thread -> (channel cc, 4 consecutive spatial)
    {
        const int cc = t >> 3;                // 0..31
        const int pp = t & 7;                 // 0..7  (x4 spatial)
        float4 v = *reinterpret_cast<const float4*>(
            src + (size_t)(c0 + cc) * HW_ + p0 + pp * 4);
        tile[pp * 4 + 0][cc] = v.x;
        tile[pp * 4 + 1][cc] = v.y;
        tile[pp * 4 + 2][cc] = v.z;
        tile[pp * 4 + 3][cc] = v.w;
    }
    __syncthreads();
    // store: thread -> (spatial ps, 4 consecutive channels)
    {
        const int ps = t >> 3;                // 0..31
        const int cs = t & 7;                 // 0..7  (x4 channel)
        float4 v;
        v.x = tile[ps][cs * 4 + 0];
        v.y = tile[ps][cs * 4 + 1];
        v.z = tile[ps][cs * 4 + 2];
        v.w = tile[ps][cs * 4 + 3];
        *reinterpret_cast<float4*>(dst + (size_t)(p0 + ps) * C_ + c0 + cs * 4) = v;
    }
}

// ---------------- kernel 2: roi_align 1x1 (adaptive grid) ----------------
// 1 block per ROI. 4 warps split gy rows; lane = 4 channels (float4 = all 128 ch/warp).
#define RA_WARPS 4
__global__ void __launch_bounds__(32 * RA_WARPS) roi_align_kernel(
    const float* __restrict__ zf,
    const float* __restrict__ bboxes,
    float* __restrict__ feats)
{
    const int warp = threadIdx.x >> 5;
    const int lane = threadIdx.x & 31;
    const int roi  = blockIdx.x;             // b*N + n
    const int b    = roi >> 6;               // N=64

    const float4 box = __ldg(reinterpret_cast<const float4*>(bboxes) + roi);
    const float x1 = box.x * SCALE - 0.5f;
    const float y1 = box.y * SCALE - 0.5f;
    const float rw = box.z * SCALE - 0.5f - x1;
    const float rh = box.w * SCALE - 0.5f - y1;
    const float gw = fminf(fmaxf(ceilf(rw), 1.f), (float)MAXG);
    const float gh = fminf(fmaxf(ceilf(rh), 1.f), (float)MAXG);
    const int igw = (int)gw, igh = (int)gh;
    const float bwx = rw / gw, bwy = rh / gh;

    __shared__ int   s_xl[MAXG], s_xh[MAXG], s_yl[MAXG], s_yh[MAXG];
    __shared__ float s_fx[MAXG], s_fy[MAXG], s_mx[MAXG], s_my[MAXG];
    __shared__ float4 s_part[RA_WARPS][32];

    // first warp: lanes 0-15 -> x coords, lanes 16-31 -> y coords (torchvision _prep_coord)
    if (warp == 0) {
        const int g    = lane & 15;
        const bool isx = lane < 16;
        const float o  = isx ? x1  : y1;
        const float bw = isx ? bwx : bwy;
        const float L  = isx ? (float)W_ : (float)H_;
        float cc0 = o + ((float)g + 0.5f) * bw;
        float inr = (cc0 > -1.0f && cc0 < L) ? 1.0f : 0.0f;
        float cc = fmaxf(cc0, 0.0f);
        int lo = min((int)floorf(cc), (int)L - 1);
        int hi = min(lo + 1, (int)L - 1);
        if (lo >= (int)L - 1) cc = (float)lo;
        float fr = cc - (float)lo;
        if (isx) { s_xl[g] = lo; s_xh[g] = hi; s_fx[g] = fr; s_mx[g] = inr; }
        else     { s_yl[g] = lo; s_yh[g] = hi; s_fy[g] = fr; s_my[g] = inr; }
    }
    __syncthreads();

    const float4* zb = reinterpret_cast<const float4*>(zf + (size_t)b * HW_ * C_);
    float4 acc = make_float4(0.f, 0.f, 0.f, 0.f);

    for (int gy = warp; gy < igh; gy += RA_WARPS) {
        const float fy = s_fy[gy], hy = 1.0f - fy;
        const float my = s_my[gy];
        const float4* r0 = zb + (size_t)s_yl[gy] * W_ * (C_ / 4) + lane;
        const float4* r1 = zb + (size_t)s_yh[gy] * W_ * (C_ / 4) + lane;
#pragma unroll 4
        for (int gx = 0; gx < igw; gx++) {
            const float fx = s_fx[gx], hx = 1.0f - fx;
            const float m   = my * s_mx[gx];
            const float w11 = m * hy * hx, w12 = m * hy * fx;
            const float w21 = m * fy * hx, w22 = m * fy * fx;
            const int xl = s_xl[gx] * (C_ / 4);
            const int xh = s_xh[gx] * (C_ / 4);
            float4 a  = __ldg(r0 + xl);
            float4 bq = __ldg(r0 + xh);
            float4 cq = __ldg(r1 + xl);
            float4 d  = __ldg(r1 + xh);
            acc.x += w11 * a.x + w12 * bq.x + w21 * cq.x + w22 * d.x;
            acc.y += w11 * a.y + w12 * bq.y + w21 * cq.y + w22 * d.y;
            acc.z += w11 * a.z + w12 * bq.z + w21 * cq.z + w22 * d.z;
            acc.w += w11 * a.w + w12 * bq.w + w21 * cq.w + w22 * d.w;
        }
    }
    s_part[warp][lane] = acc;
    __syncthreads();

    if (warp == 0) {
        float4 p0 = s_part[0][lane], p1 = s_part[1][lane];
        float4 p2 = s_part[2][lane], p3 = s_part[3][lane];
        const float inv = 1.0f / (gw * gh);
        float4 r;
        r.x = (p0.x + p1.x + p2.x + p3.x) * inv;
        r.y = (p0.y + p1.y + p2.y + p3.y) * inv;
        r.z = (p0.z + p1.z + p2.z + p3.z) * inv;
        r.w = (p0.w + p1.w + p2.w + p3.w) * inv;
        reinterpret_cast<float4*>(feats)[roi * (C_ / 4) + lane] = r;
    }
}

// ---------------- kernel 3: feats[1024,128] @ W^T[128,256] + b ----------------
// 8 ROIs per block, 128 blocks, 256 threads (one output channel each).
#define ROIS_PB 8
__global__ void __launch_bounds__(OUT_) gemm_kernel(
    const float* __restrict__ feats,
    const float* __restrict__ Wm,      // [256,128]
    const float* __restrict__ bias,    // [256]
    float* __restrict__ out)           // [1024,256]
{
    __shared__ float fs[ROIS_PB][C_];
    const int r0  = blockIdx.x * ROIS_PB;
    const int tid = threadIdx.x;

    // 8*128 floats = 256 float4s, 256 threads -> 1 iter
    reinterpret_cast<float4*>(&fs[0][0])[tid] =
        reinterpret_cast<const float4*>(feats + (size_t)r0 * C_)[tid];
    __syncthreads();

    const int oc = tid;
    const float bv = bias[oc];
    float acc[ROIS_PB];
#pragma unroll
    for (int r = 0; r < ROIS_PB; r++) acc[r] = bv;

    const float4* wrow = reinterpret_cast<const float4*>(Wm + (size_t)oc * C_);
#pragma unroll
    for (int c4 = 0; c4 < C_ / 4; c4 += 2) {
        float4 w0 = wrow[c4], w1 = wrow[c4 + 1];
#pragma unroll
        for (int r = 0; r < ROIS_PB; r++) {
            float4 f0 = reinterpret_cast<const float4*>(&fs[r][0])[c4];
            float4 f1 = reinterpret_cast<const float4*>(&fs[r][0])[c4 + 1];
            acc[r] += w0.x * f0.x + w0.y * f0.y + w0.z * f0.z + w0.w * f0.w
                    + w1.x * f1.x + w1.y * f1.y + w1.z * f1.z + w1.w * f1.w;
        }
    }
#pragma unroll
    for (int r = 0; r < ROIS_PB; r++)
        out[(size_t)(r0 + r) * OUT_ + oc] = acc[r];
}

// ---------------- launch ----------------
extern "C" void kernel_launch(void* const* d_in, const int* in_sizes, int n_in,
                              void* d_out, int out_size) {
    const float* z      = (const float*)d_in[0];  // [16,128,64,64]
    const float* bboxes = (const float*)d_in[1];  // [16,64,4]
    const float* Wm     = (const float*)d_in[2];  // [256,128]
    const float* bias   = (const float*)d_in[3];  // [256]
    float* out = (float*)d_out;                   // [16,64,256]

    float* zf;    cudaGetSymbolAddress((void**)&zf,    g_zf);
    float* feats; cudaGetSymbolAddress((void**)&feats, g_feats);

    dim3 tgrid(HW_ / 32, C_ / 32, B_);
    transpose_kernel<<<tgrid, 256>>>(z, zf);

    roi_align_kernel<<<NROI, 32 * RA_WARPS>>>(zf, bboxes, feats);

    gemm_kernel<<<NROI / ROIS_PB, OUT_>>>(feats, Wm, bias, out);
}

// round 7
// speedup vs baseline: 2.6181x; 1.6650x over previous
#include <cuda_runtime.h>
#include <cuda_bf16.h>
#include <cstdint>

#define B_    16
#define N_    64
#define C_    128
#define H_    64
#define W_    64
#define HW_   (H_ * W_)           // 4096
#define OUT_  256
#define NROI  (B_ * N_)           // 1024
#define SCALE 0.125f
#define MAXG  16
#define MAXCELL 20                // max footprint cells per axis (<=18 actual)

// ---------------- scratch (no allocations allowed) ----------------
__device__ float g_zf[B_ * HW_ * C_];      // [B,H,W,C]  32 MB
__device__ float g_feats[NROI * C_];       // [1024,128] 512 KB

// ---------------- kernel 1: NCHW -> NHWC transpose ----------------
// (measured-best 13.2us scalar 32x32 tile version)
__global__ void transpose_kernel(const float* __restrict__ z, float* __restrict__ zf) {
    __shared__ float tile[32][33];
    const int b  = blockIdx.z;
    const int p0 = blockIdx.x * 32;   // spatial
    const int c0 = blockIdx.y * 32;   // channel
    const int tx = threadIdx.x, ty = threadIdx.y;

    const float* src = z  + (size_t)b * C_ * HW_;
    float*       dst = zf + (size_t)b * HW_ * C_;

#pragma unroll
    for (int i = 0; i < 32; i += 8)
        tile[ty + i][tx] = src[(size_t)(c0 + ty + i) * HW_ + (p0 + tx)];
    __syncthreads();
#pragma unroll
    for (int i = 0; i < 32; i += 8)
        dst[(size_t)(p0 + ty + i) * C_ + (c0 + tx)] = tile[tx][ty + i];
}

// ---------------- kernel 2: roi_align 1x1, separable-weight form ------------
// Bilinear + adaptive-grid sum is exactly separable:
//   out[c] = (1/(gh*gw)) * sum_Y wy[Y] * sum_X wx[X] * z[Y,X,c]
// wy/wx are 1-D weights accumulated over the ROI's unique footprint cells.
// One weighted float4 load per unique cell instead of 4 per (gy,gx) sample.
#define RA_WARPS 4
__global__ void __launch_bounds__(32 * RA_WARPS) roi_align_kernel(
    const float* __restrict__ zf,
    const float* __restrict__ bboxes,
    float* __restrict__ feats)
{
    const int warp = threadIdx.x >> 5;
    const int lane = threadIdx.x & 31;
    const int roi  = blockIdx.x;             // b*N + n
    const int b    = roi >> 6;               // N=64

    const float4 box = __ldg(reinterpret_cast<const float4*>(bboxes) + roi);
    const float x1 = box.x * SCALE - 0.5f;
    const float y1 = box.y * SCALE - 0.5f;
    const float rw = box.z * SCALE - 0.5f - x1;
    const float rh = box.w * SCALE - 0.5f - y1;
    const float gw = fminf(fmaxf(ceilf(rw), 1.f), (float)MAXG);
    const float gh = fminf(fmaxf(ceilf(rh), 1.f), (float)MAXG);
    const int igw = (int)gw, igh = (int)gh;
    const float bwx = rw / gw, bwy = rh / gh;

    __shared__ float s_wx[MAXCELL], s_wy[MAXCELL];
    __shared__ int   s_x0, s_y0, s_nx, s_ny;
    __shared__ float4 s_part[RA_WARPS][32];

    // zero weight tables
    if (threadIdx.x < 2 * MAXCELL)
        (threadIdx.x < MAXCELL ? s_wx : s_wy)[threadIdx.x % MAXCELL] = 0.0f;
    __syncthreads();

    // warp 0 builds the 1-D weight tables (torchvision _prep_coord semantics).
    // lanes 0-15: x grid points; lanes 16-31: y grid points.
    if (warp == 0) {
        const int g    = lane & 15;
        const bool isx = lane < 16;
        const float o  = isx ? x1  : y1;
        const float bw = isx ? bwx : bwy;
        const int  ig  = isx ? igw : igh;
        const float L  = isx ? (float)W_ : (float)H_;

        float cc0 = o + ((float)g + 0.5f) * bw;
        float inr = (cc0 > -1.0f && cc0 < L) ? 1.0f : 0.0f;
        float cc = fmaxf(cc0, 0.0f);
        int lo = min((int)floorf(cc), (int)L - 1);
        int hi = min(lo + 1, (int)L - 1);
        if (lo >= (int)L - 1) cc = (float)lo;
        float fr = cc - (float)lo;

        // base cell = lo at g==0 (sample coords monotonic nondecreasing in g)
        int base = __shfl_sync(0xFFFFFFFFu, lo, isx ? 0 : 16);
        // extent = max over active lanes of hi - base + 1 (half-warp reduction;
        // xor with s<=8 never crosses the 16-lane half boundary)
        int ext = (g < ig) ? (hi - base + 1) : 1;
#pragma unroll
        for (int s = 8; s >= 1; s >>= 1)
            ext = max(ext, __shfl_xor_sync(0xFFFFFFFFu, ext, s));
        if (lane == 0)  { s_x0 = base; s_nx = ext; }
        if (lane == 16) { s_y0 = base; s_ny = ext; }

        if (g < ig) {
            float* wtab = isx ? s_wx : s_wy;
            atomicAdd(&wtab[lo - base], inr * (1.0f - fr));
            atomicAdd(&wtab[hi - base], inr * fr);
        }
    }
    __syncthreads();

    const int x0 = s_x0, y0 = s_y0, nx = s_nx, ny = s_ny;
    const float inv = 1.0f / (gw * gh);
    const float4* zb = reinterpret_cast<const float4*>(zf + (size_t)b * HW_ * C_);

    // two independent accumulator chains for ILP
    float4 acc0 = make_float4(0.f, 0.f, 0.f, 0.f);
    float4 acc1 = make_float4(0.f, 0.f, 0.f, 0.f);

    for (int yc = warp; yc < ny; yc += RA_WARPS) {
        const float wy = s_wy[yc] * inv;     // fold normalization into wy
        const float4* row = zb + (size_t)(y0 + yc) * W_ * (C_ / 4) + x0 * (C_ / 4) + lane;
        int xc = 0;
#pragma unroll 4
        for (; xc + 2 <= nx; xc += 2) {
            const float w0 = wy * s_wx[xc];
            const float w1 = wy * s_wx[xc + 1];
            float4 v0 = __ldg(row + xc * (C_ / 4));
            float4 v1 = __ldg(row + (xc + 1) * (C_ / 4));
            acc0.x += w0 * v0.x;  acc1.x += w1 * v1.x;
            acc0.y += w0 * v0.y;  acc1.y += w1 * v1.y;
            acc0.z += w0 * v0.z;  acc1.z += w1 * v1.z;
            acc0.w += w0 * v0.w;  acc1.w += w1 * v1.w;
        }
        if (xc < nx) {
            const float w0 = wy * s_wx[xc];
            float4 v0 = __ldg(row + xc * (C_ / 4));
            acc0.x += w0 * v0.x;
            acc0.y += w0 * v0.y;
            acc0.z += w0 * v0.z;
            acc0.w += w0 * v0.w;
        }
    }
    acc0.x += acc1.x; acc0.y += acc1.y; acc0.z += acc1.z; acc0.w += acc1.w;
    s_part[warp][lane] = acc0;
    __syncthreads();

    if (warp == 0) {
        float4 p0 = s_part[0][lane], p1 = s_part[1][lane];
        float4 p2 = s_part[2][lane], p3 = s_part[3][lane];
        float4 r;
        r.x = (p0.x + p1.x) + (p2.x + p3.x);
        r.y = (p0.y + p1.y) + (p2.y + p3.y);
        r.z = (p0.z + p1.z) + (p2.z + p3.z);
        r.w = (p0.w + p1.w) + (p2.w + p3.w);
        reinterpret_cast<float4*>(feats)[roi * (C_ / 4) + lane] = r;
    }
}

// ---------------- kernel 3: feats[1024,128] @ W^T[128,256] + b ----------------
#define ROIS_PB 8
__global__ void __launch_bounds__(OUT_) gemm_kernel(
    const float* __restrict__ feats,
    const float* __restrict__ Wm,      // [256,128]
    const float* __restrict__ bias,    // [256]
    float* __restrict__ out)           // [1024,256]
{
    __shared__ float fs[ROIS_PB][C_];
    const int r0  = blockIdx.x * ROIS_PB;
    const int tid = threadIdx.x;

    reinterpret_cast<float4*>(&fs[0][0])[tid] =
        reinterpret_cast<const float4*>(feats + (size_t)r0 * C_)[tid];
    __syncthreads();

    const int oc = tid;
    const float bv = bias[oc];
    float acc[ROIS_PB];
#pragma unroll
    for (int r = 0; r < ROIS_PB; r++) acc[r] = bv;

    const float4* wrow = reinterpret_cast<const float4*>(Wm + (size_t)oc * C_);
#pragma unroll
    for (int c4 = 0; c4 < C_ / 4; c4 += 2) {
        float4 w0 = wrow[c4], w1 = wrow[c4 + 1];
#pragma unroll
        for (int r = 0; r < ROIS_PB; r++) {
            float4 f0 = reinterpret_cast<const float4*>(&fs[r][0])[c4];
            float4 f1 = reinterpret_cast<const float4*>(&fs[r][0])[c4 + 1];
            acc[r] += w0.x * f0.x + w0.y * f0.y + w0.z * f0.z + w0.w * f0.w
                    + w1.x * f1.x + w1.y * f1.y + w1.z * f1.z + w1.w * f1.w;
        }
    }
#pragma unroll
    for (int r = 0; r < ROIS_PB; r++)
        out[(size_t)(r0 + r) * OUT_ + oc] = acc[r];
}

// ---------------- launch ----------------
extern "C" void kernel_launch(void* const* d_in, const int* in_sizes, int n_in,
                              void* d_out, int out_size) {
    const float* z      = (const float*)d_in[0];  // [16,128,64,64]
    const float* bboxes = (const float*)d_in[1];  // [16,64,4]
    const float* Wm     = (const float*)d_in[2];  // [256,128]
    const float* bias   = (const float*)d_in[3];  // [256]
    float* out = (float*)d_out;                   // [16,64,256]

    float* zf;    cudaGetSymbolAddress((void**)&zf,    g_zf);
    float* feats; cudaGetSymbolAddress((void**)&feats, g_feats);

    dim3 tgrid(HW_ / 32, C_ / 32, B_);
    transpose_kernel<<<tgrid, dim3(32, 8)>>>(z, zf);

    roi_align_kernel<<<NROI, 32 * RA_WARPS>>>(zf, bboxes, feats);

    gemm_kernel<<<NROI / ROIS_PB, OUT_>>>(feats, Wm, bias, out);
}

// round 13
// speedup vs baseline: 2.8222x; 1.0779x over previous
#include <cuda_runtime.h>
#include <cuda_bf16.h>
#include <cstdint>

#define B_    16
#define N_    64
#define C_    128
#define H_    64
#define W_    64
#define HW_   (H_ * W_)           // 4096
#define OUT_  256
#define NROI  (B_ * N_)           // 1024
#define SCALE 0.125f
#define MAXG  16
#define MAXCELL 20                // max footprint cells per axis (<=18 actual)
#define RA_SPLIT 4                // blocks per ROI
#define RA_WARPS 4                // warps per block
#define TP_TILES 4                // 32x32 tiles per transpose block

// ---------------- scratch (no allocations allowed) ----------------
__device__ float g_zf[B_ * HW_ * C_];                 // [B,H,W,C]  32 MB
__device__ float g_part[NROI * RA_SPLIT * C_];        // partial feats, 2 MB

// ---------------- kernel 1: NCHW -> NHWC transpose, 4 tiles/block -----------
// 2048 blocks (<2 waves) instead of 8192 (~7 waves); 16 LDGs in flight per
// thread before a single __syncthreads.
__global__ void __launch_bounds__(256) transpose_kernel(
    const float* __restrict__ z, float* __restrict__ zf)
{
    __shared__ float tile[TP_TILES][32][33];
    const int b  = blockIdx.z;
    const int p0 = blockIdx.x * (32 * TP_TILES);  // spatial base (128 wide)
    const int c0 = blockIdx.y * 32;               // channel base
    const int tx = threadIdx.x, ty = threadIdx.y;

    const float* src = z  + (size_t)b * C_ * HW_;
    float*       dst = zf + (size_t)b * HW_ * C_;

#pragma unroll
    for (int t = 0; t < TP_TILES; t++)
#pragma unroll
        for (int i = 0; i < 32; i += 8)
            tile[t][ty + i][tx] = src[(size_t)(c0 + ty + i) * HW_ + p0 + 32 * t + tx];
    __syncthreads();
#pragma unroll
    for (int t = 0; t < TP_TILES; t++)
#pragma unroll
        for (int i = 0; i < 32; i += 8)
            dst[(size_t)(p0 + 32 * t + ty + i) * C_ + c0 + tx] = tile[t][tx][ty + i];
}

// ---------------- kernel 2: roi_align 1x1, separable + ROI-split ------------
// out[c] = (1/(gh*gw)) * sum_Y wy[Y] * sum_X wx[X] * z[Y,X,c]
// Each ROI is processed by RA_SPLIT blocks; the 16 warps across those blocks
// take footprint rows strided by 16 (fixes the 4..289-cell load imbalance).
// Partials are reduced deterministically in the GEMM.
__global__ void __launch_bounds__(32 * RA_WARPS) roi_align_kernel(
    const float* __restrict__ zf,
    const float* __restrict__ bboxes,
    float* __restrict__ part)
{
    const int warp = threadIdx.x >> 5;
    const int lane = threadIdx.x & 31;
    const int roi  = blockIdx.x;             // b*N + n
    const int q    = blockIdx.y;             // split index 0..RA_SPLIT-1
    const int b    = roi >> 6;               // N=64

    const float4 box = __ldg(reinterpret_cast<const float4*>(bboxes) + roi);
    const float x1 = box.x * SCALE - 0.5f;
    const float y1 = box.y * SCALE - 0.5f;
    const float rw = box.z * SCALE - 0.5f - x1;
    const float rh = box.w * SCALE - 0.5f - y1;
    const float gw = fminf(fmaxf(ceilf(rw), 1.f), (float)MAXG);
    const float gh = fminf(fmaxf(ceilf(rh), 1.f), (float)MAXG);
    const int igw = (int)gw, igh = (int)gh;
    const float bwx = rw / gw, bwy = rh / gh;

    __shared__ float s_wx[MAXCELL], s_wy[MAXCELL];
    __shared__ int   s_x0, s_y0, s_nx, s_ny;
    __shared__ float4 s_part[RA_WARPS][32];

    if (threadIdx.x < 2 * MAXCELL)
        (threadIdx.x < MAXCELL ? s_wx : s_wy)[threadIdx.x % MAXCELL] = 0.0f;
    __syncthreads();

    // warp 0 builds the 1-D weight tables (torchvision _prep_coord semantics).
    // lanes 0-15: x grid points; lanes 16-31: y grid points.
    if (warp == 0) {
        const int g    = lane & 15;
        const bool isx = lane < 16;
        const float o  = isx ? x1  : y1;
        const float bw = isx ? bwx : bwy;
        const int  ig  = isx ? igw : igh;
        const float L  = isx ? (float)W_ : (float)H_;

        float cc0 = o + ((float)g + 0.5f) * bw;
        float inr = (cc0 > -1.0f && cc0 < L) ? 1.0f : 0.0f;
        float cc = fmaxf(cc0, 0.0f);
        int lo = min((int)floorf(cc), (int)L - 1);
        int hi = min(lo + 1, (int)L - 1);
        if (lo >= (int)L - 1) cc = (float)lo;
        float fr = cc - (float)lo;

        // base cell = lo at g==0 (sample coords monotonic nondecreasing in g)
        int base = __shfl_sync(0xFFFFFFFFu, lo, isx ? 0 : 16);
        // extent = max over active lanes of hi - base + 1 (half-warp reduce;
        // xor with s<=8 never crosses the 16-lane half boundary)
        int ext = (g < ig) ? (hi - base + 1) : 1;
#pragma unroll
        for (int s = 8; s >= 1; s >>= 1)
            ext = max(ext, __shfl_xor_sync(0xFFFFFFFFu, ext, s));
        if (lane == 0)  { s_x0 = base; s_nx = ext; }
        if (lane == 16) { s_y0 = base; s_ny = ext; }

        if (g < ig) {
            float* wtab = isx ? s_wx : s_wy;
            atomicAdd(&wtab[lo - base], inr * (1.0f - fr));
            atomicAdd(&wtab[hi - base], inr * fr);
        }
    }
    __syncthreads();

    const int x0 = s_x0, y0 = s_y0, nx = s_nx, ny = s_ny;
    const float inv = 1.0f / (gw * gh);
    const float4* zb = reinterpret_cast<const float4*>(zf + (size_t)b * HW_ * C_);

    float4 acc0 = make_float4(0.f, 0.f, 0.f, 0.f);
    float4 acc1 = make_float4(0.f, 0.f, 0.f, 0.f);

    // rows strided by RA_SPLIT*RA_WARPS = 16 across the ROI's 16 warps
    for (int yc = q * RA_WARPS + warp; yc < ny; yc += RA_SPLIT * RA_WARPS) {
        const float wy = s_wy[yc] * inv;
        const float4* row = zb + (size_t)(y0 + yc) * W_ * (C_ / 4) + x0 * (C_ / 4) + lane;
        int xc = 0;
#pragma unroll 4
        for (; xc + 2 <= nx; xc += 2) {
            const float w0 = wy * s_wx[xc];
            const float w1 = wy * s_wx[xc + 1];
            float4 v0 = __ldg(row + xc * (C_ / 4));
            float4 v1 = __ldg(row + (xc + 1) * (C_ / 4));
            acc0.x += w0 * v0.x;  acc1.x += w1 * v1.x;
            acc0.y += w0 * v0.y;  acc1.y += w1 * v1.y;
            acc0.z += w0 * v0.z;  acc1.z += w1 * v1.z;
            acc0.w += w0 * v0.w;  acc1.w += w1 * v1.w;
        }
        if (xc < nx) {
            const float w0 = wy * s_wx[xc];
            float4 v0 = __ldg(row + xc * (C_ / 4));
            acc0.x += w0 * v0.x;
            acc0.y += w0 * v0.y;
            acc0.z += w0 * v0.z;
            acc0.w += w0 * v0.w;
        }
    }
    acc0.x += acc1.x; acc0.y += acc1.y; acc0.z += acc1.z; acc0.w += acc1.w;
    s_part[warp][lane] = acc0;
    __syncthreads();

    if (warp == 0) {
        float4 p0 = s_part[0][lane], p1 = s_part[1][lane];
        float4 p2 = s_part[2][lane], p3 = s_part[3][lane];
        float4 r;
        r.x = (p0.x + p1.x) + (p2.x + p3.x);
        r.y = (p0.y + p1.y) + (p2.y + p3.y);
        r.z = (p0.z + p1.z) + (p2.z + p3.z);
        r.w = (p0.w + p1.w) + (p2.w + p3.w);
        reinterpret_cast<float4*>(part)[(roi * RA_SPLIT + q) * (C_ / 4) + lane] = r;
    }
}

// ---------------- kernel 3: (sum partials) @ W^T[128,256] + b ----------------
#define ROIS_PB 8
__global__ void __launch_bounds__(OUT_) gemm_kernel(
    const float* __restrict__ part,    // [NROI][RA_SPLIT][C_]
    const float* __restrict__ Wm,      // [256,128]
    const float* __restrict__ bias,    // [256]
    float* __restrict__ out)           // [1024,256]
{
    __shared__ float fs[ROIS_PB][C_];
    const int r0  = blockIdx.x * ROIS_PB;
    const int tid = threadIdx.x;

    // reduce RA_SPLIT partials while filling smem: 8 ROIs * 32 float4 = 256
    {
        const int r  = tid >> 5;            // 0..7
        const int c4 = tid & 31;            // 0..31
        const float4* pp = reinterpret_cast<const float4*>(part)
                         + (size_t)(r0 + r) * RA_SPLIT * (C_ / 4) + c4;
        float4 a = pp[0 * (C_ / 4)];
        float4 b = pp[1 * (C_ / 4)];
        float4 c = pp[2 * (C_ / 4)];
        float4 d = pp[3 * (C_ / 4)];
        float4 s;
        s.x = (a.x + b.x) + (c.x + d.x);
        s.y = (a.y + b.y) + (c.y + d.y);
        s.z = (a.z + b.z) + (c.z + d.z);
        s.w = (a.w + b.w) + (c.w + d.w);
        reinterpret_cast<float4*>(&fs[r][0])[c4] = s;
    }
    __syncthreads();

    const int oc = tid;
    const float bv = bias[oc];
    float acc[ROIS_PB];
#pragma unroll
    for (int r = 0; r < ROIS_PB; r++) acc[r] = bv;

    const float4* wrow = reinterpret_cast<const float4*>(Wm + (size_t)oc * C_);
#pragma unroll
    for (int c4 = 0; c4 < C_ / 4; c4 += 2) {
        float4 w0 = wrow[c4], w1 = wrow[c4 + 1];
#pragma unroll
        for (int r = 0; r < ROIS_PB; r++) {
            float4 f0 = reinterpret_cast<const float4*>(&fs[r][0])[c4];
            float4 f1 = reinterpret_cast<const float4*>(&fs[r][0])[c4 + 1];
            acc[r] += w0.x * f0.x + w0.y * f0.y + w0.z * f0.z + w0.w * f0.w
                    + w1.x * f1.x + w1.y * f1.y + w1.z * f1.z + w1.w * f1.w;
        }
    }
#pragma unroll
    for (int r = 0; r < ROIS_PB; r++)
        out[(size_t)(r0 + r) * OUT_ + oc] = acc[r];
}

// ---------------- launch ----------------
extern "C" void kernel_launch(void* const* d_in, const int* in_sizes, int n_in,
                              void* d_out, int out_size) {
    const float* z      = (const float*)d_in[0];  // [16,128,64,64]
    const float* bboxes = (const float*)d_in[1];  // [16,64,4]
    const float* Wm     = (const float*)d_in[2];  // [256,128]
    const float* bias   = (const float*)d_in[3];  // [256]
    float* out = (float*)d_out;                   // [16,64,256]

    float* zf;   cudaGetSymbolAddress((void**)&zf,   g_zf);
    float* part; cudaGetSymbolAddress((void**)&part, g_part);

    dim3 tgrid(HW_ / (32 * TP_TILES), C_ / 32, B_);   // (32, 4, 16) = 2048 blocks
    transpose_kernel<<<tgrid, dim3(32, 8)>>>(z, zf);

    roi_align_kernel<<<dim3(NROI, RA_SPLIT), 32 * RA_WARPS>>>(zf, bboxes, part);

    gemm_kernel<<<NROI / ROIS_PB, OUT_>>>(part, Wm, bias, out);
}

// round 14
// speedup vs baseline: 3.0354x; 1.0756x over previous
#include <cuda_runtime.h>
#include <cuda_fp16.h>
#include <cstdint>

#define B_    16
#define N_    64
#define C_    128
#define H_    64
#define W_    64
#define HW_   (H_ * W_)           // 4096
#define OUT_  256
#define NROI  (B_ * N_)           // 1024
#define SCALE 0.125f
#define MAXG  16
#define MAXCELL 20                // max footprint cells per axis (<=18 actual)
#define RA_SPLIT 4                // blocks per ROI
#define RA_WARPS 4                // warps per block
#define TP_TILES 4                // 32x32 tiles per transpose block

// ---------------- scratch (no allocations allowed) ----------------
__device__ __half g_zh[B_ * HW_ * C_];                // [B,H,W,C] fp16, 16.8 MB
__device__ float  g_part[NROI * RA_SPLIT * C_];       // partial feats, 2 MB

// ---------------- kernel 1: NCHW fp32 -> NHWC fp16 transpose ---------------
// Load side identical to measured-best scalar version. Store side packs 4
// channels into one 8-byte STG (half the write bytes, 4x fewer stores).
__global__ void __launch_bounds__(256) transpose_kernel(
    const float* __restrict__ z, __half* __restrict__ zh)
{
    __shared__ float tile[TP_TILES][32][33];   // [tile][channel][spatial]
    const int b  = blockIdx.z;
    const int p0 = blockIdx.x * (32 * TP_TILES);  // spatial base (128 wide)
    const int c0 = blockIdx.y * 32;               // channel base
    const int tx = threadIdx.x, ty = threadIdx.y;

    const float* src = z  + (size_t)b * C_ * HW_;
    __half*      dst = zh + (size_t)b * HW_ * C_;

#pragma unroll
    for (int t = 0; t < TP_TILES; t++)
#pragma unroll
        for (int i = 0; i < 32; i += 8)
            tile[t][ty + i][tx] = src[(size_t)(c0 + ty + i) * HW_ + p0 + 32 * t + tx];
    __syncthreads();

    // store: thread -> (spatial ps, channel quad cq), 4 ch packed as 2x half2
    const int t  = ty * 32 + tx;        // 0..255
    const int cq = t & 7;               // 0..7  (channel quad)
    const int ps = t >> 3;              // 0..31 (spatial)
#pragma unroll
    for (int tt = 0; tt < TP_TILES; tt++) {
        float v0 = tile[tt][4 * cq + 0][ps];
        float v1 = tile[tt][4 * cq + 1][ps];
        float v2 = tile[tt][4 * cq + 2][ps];
        float v3 = tile[tt][4 * cq + 3][ps];
        __half2 h0 = __floats2half2_rn(v0, v1);
        __half2 h1 = __floats2half2_rn(v2, v3);
        uint2 u;
        u.x = *reinterpret_cast<unsigned int*>(&h0);
        u.y = *reinterpret_cast<unsigned int*>(&h1);
        *reinterpret_cast<uint2*>(dst + (size_t)(p0 + 32 * tt + ps) * C_ + c0 + 4 * cq) = u;
    }
}

// ---------------- kernel 2: roi_align 1x1, separable + ROI-split, fp16 ------
// out[c] = (1/(gh*gw)) * sum_Y wy[Y] * sum_X wx[X] * z[Y,X,c]
// One cell = 128 ch fp16 = 256B: ONE uint2 warp-load covers all channels.
__global__ void __launch_bounds__(32 * RA_WARPS) roi_align_kernel(
    const __half* __restrict__ zh,
    const float* __restrict__ bboxes,
    float* __restrict__ part)
{
    const int warp = threadIdx.x >> 5;
    const int lane = threadIdx.x & 31;
    const int roi  = blockIdx.x;             // b*N + n
    const int q    = blockIdx.y;             // split index 0..RA_SPLIT-1
    const int b    = roi >> 6;               // N=64

    const float4 box = __ldg(reinterpret_cast<const float4*>(bboxes) + roi);
    const float x1 = box.x * SCALE - 0.5f;
    const float y1 = box.y * SCALE - 0.5f;
    const float rw = box.z * SCALE - 0.5f - x1;
    const float rh = box.w * SCALE - 0.5f - y1;
    const float gw = fminf(fmaxf(ceilf(rw), 1.f), (float)MAXG);
    const float gh = fminf(fmaxf(ceilf(rh), 1.f), (float)MAXG);
    const int igw = (int)gw, igh = (int)gh;
    const float bwx = rw / gw, bwy = rh / gh;

    __shared__ float s_wx[MAXCELL], s_wy[MAXCELL];
    __shared__ int   s_x0, s_y0, s_nx, s_ny;
    __shared__ float4 s_part[RA_WARPS][32];

    if (threadIdx.x < 2 * MAXCELL)
        (threadIdx.x < MAXCELL ? s_wx : s_wy)[threadIdx.x % MAXCELL] = 0.0f;
    __syncthreads();

    // warp 0 builds the 1-D weight tables (torchvision _prep_coord semantics).
    // lanes 0-15: x grid points; lanes 16-31: y grid points.
    if (warp == 0) {
        const int g    = lane & 15;
        const bool isx = lane < 16;
        const float o  = isx ? x1  : y1;
        const float bw = isx ? bwx : bwy;
        const int  ig  = isx ? igw : igh;
        const float L  = isx ? (float)W_ : (float)H_;

        float cc0 = o + ((float)g + 0.5f) * bw;
        float inr = (cc0 > -1.0f && cc0 < L) ? 1.0f : 0.0f;
        float cc = fmaxf(cc0, 0.0f);
        int lo = min((int)floorf(cc), (int)L - 1);
        int hi = min(lo + 1, (int)L - 1);
        if (lo >= (int)L - 1) cc = (float)lo;
        float fr = cc - (float)lo;

        // base cell = lo at g==0 (sample coords monotonic nondecreasing in g)
        int base = __shfl_sync(0xFFFFFFFFu, lo, isx ? 0 : 16);
        // extent = max over active lanes of hi - base + 1 (half-warp reduce)
        int ext = (g < ig) ? (hi - base + 1) : 1;
#pragma unroll
        for (int s = 8; s >= 1; s >>= 1)
            ext = max(ext, __shfl_xor_sync(0xFFFFFFFFu, ext, s));
        if (lane == 0)  { s_x0 = base; s_nx = ext; }
        if (lane == 16) { s_y0 = base; s_ny = ext; }

        if (g < ig) {
            float* wtab = isx ? s_wx : s_wy;
            atomicAdd(&wtab[lo - base], inr * (1.0f - fr));
            atomicAdd(&wtab[hi - base], inr * fr);
        }
    }
    __syncthreads();

    const int x0 = s_x0, y0 = s_y0, nx = s_nx, ny = s_ny;
    const float inv = 1.0f / (gw * gh);
    // cell = 128 halves = 32 uint2; lane covers channels 4*lane..4*lane+3
    const uint2* zb = reinterpret_cast<const uint2*>(zh + (size_t)b * HW_ * C_);

    float4 acc0 = make_float4(0.f, 0.f, 0.f, 0.f);
    float4 acc1 = make_float4(0.f, 0.f, 0.f, 0.f);

    // rows strided by RA_SPLIT*RA_WARPS = 16 across the ROI's 16 warps
    for (int yc = q * RA_WARPS + warp; yc < ny; yc += RA_SPLIT * RA_WARPS) {
        const float wy = s_wy[yc] * inv;
        const uint2* row = zb + ((size_t)(y0 + yc) * W_ + x0) * 32 + lane;
        int xc = 0;
#pragma unroll 4
        for (; xc + 2 <= nx; xc += 2) {
            const float w0 = wy * s_wx[xc];
            const float w1 = wy * s_wx[xc + 1];
            uint2 u0 = __ldg(row + xc * 32);
            uint2 u1 = __ldg(row + (xc + 1) * 32);
            float2 a0 = __half22float2(*reinterpret_cast<const __half2*>(&u0.x));
            float2 a1 = __half22float2(*reinterpret_cast<const __half2*>(&u0.y));
            float2 b0 = __half22float2(*reinterpret_cast<const __half2*>(&u1.x));
            float2 b1 = __half22float2(*reinterpret_cast<const __half2*>(&u1.y));
            acc0.x += w0 * a0.x;  acc1.x += w1 * b0.x;
            acc0.y += w0 * a0.y;  acc1.y += w1 * b0.y;
            acc0.z += w0 * a1.x;  acc1.z += w1 * b1.x;
            acc0.w += w0 * a1.y;  acc1.w += w1 * b1.y;
        }
        if (xc < nx) {
            const float w0 = wy * s_wx[xc];
            uint2 u0 = __ldg(row + xc * 32);
            float2 a0 = __half22float2(*reinterpret_cast<const __half2*>(&u0.x));
            float2 a1 = __half22float2(*reinterpret_cast<const __half2*>(&u0.y));
            acc0.x += w0 * a0.x;
            acc0.y += w0 * a0.y;
            acc0.z += w0 * a1.x;
            acc0.w += w0 * a1.y;
        }
    }
    acc0.x += acc1.x; acc0.y += acc1.y; acc0.z += acc1.z; acc0.w += acc1.w;
    s_part[warp][lane] = acc0;
    __syncthreads();

    if (warp == 0) {
        float4 p0 = s_part[0][lane], p1 = s_part[1][lane];
        float4 p2 = s_part[2][lane], p3 = s_part[3][lane];
        float4 r;
        r.x = (p0.x + p1.x) + (p2.x + p3.x);
        r.y = (p0.y + p1.y) + (p2.y + p3.y);
        r.z = (p0.z + p1.z) + (p2.z + p3.z);
        r.w = (p0.w + p1.w) + (p2.w + p3.w);
        reinterpret_cast<float4*>(part)[(roi * RA_SPLIT + q) * (C_ / 4) + lane] = r;
    }
}

// ---------------- kernel 3: (sum partials) @ W^T[128,256] + b ----------------
#define ROIS_PB 8
__global__ void __launch_bounds__(OUT_) gemm_kernel(
    const float* __restrict__ part,    // [NROI][RA_SPLIT][C_]
    const float* __restrict__ Wm,      // [256,128]
    const float* __restrict__ bias,    // [256]
    float* __restrict__ out)           // [1024,256]
{
    __shared__ float fs[ROIS_PB][C_];
    const int r0  = blockIdx.x * ROIS_PB;
    const int tid = threadIdx.x;

    // reduce RA_SPLIT partials while filling smem: 8 ROIs * 32 float4 = 256
    {
        const int r  = tid >> 5;            // 0..7
        const int c4 = tid & 31;            // 0..31
        const float4* pp = reinterpret_cast<const float4*>(part)
                         + (size_t)(r0 + r) * RA_SPLIT * (C_ / 4) + c4;
        float4 a = pp[0 * (C_ / 4)];
        float4 b = pp[1 * (C_ / 4)];
        float4 c = pp[2 * (C_ / 4)];
        float4 d = pp[3 * (C_ / 4)];
        float4 s;
        s.x = (a.x + b.x) + (c.x + d.x);
        s.y = (a.y + b.y) + (c.y + d.y);
        s.z = (a.z + b.z) + (c.z + d.z);
        s.w = (a.w + b.w) + (c.w + d.w);
        reinterpret_cast<float4*>(&fs[r][0])[c4] = s;
    }
    __syncthreads();

    const int oc = tid;
    const float bv = bias[oc];
    float acc[ROIS_PB];
#pragma unroll
    for (int r = 0; r < ROIS_PB; r++) acc[r] = bv;

    const float4* wrow = reinterpret_cast<const float4*>(Wm + (size_t)oc * C_);
#pragma unroll
    for (int c4 = 0; c4 < C_ / 4; c4 += 2) {
        float4 w0 = wrow[c4], w1 = wrow[c4 + 1];
#pragma unroll
        for (int r = 0; r < ROIS_PB; r++) {
            float4 f0 = reinterpret_cast<const float4*>(&fs[r][0])[c4];
            float4 f1 = reinterpret_cast<const float4*>(&fs[r][0])[c4 + 1];
            acc[r] += w0.x * f0.x + w0.y * f0.y + w0.z * f0.z + w0.w * f0.w
                    + w1.x * f1.x + w1.y * f1.y + w1.z * f1.z + w1.w * f1.w;
        }
    }
#pragma unroll
    for (int r = 0; r < ROIS_PB; r++)
        out[(size_t)(r0 + r) * OUT_ + oc] = acc[r];
}

// ---------------- launch ----------------
extern "C" void kernel_launch(void* const* d_in, const int* in_sizes, int n_in,
                              void* d_out, int out_size) {
    const float* z      = (const float*)d_in[0];  // [16,128,64,64]
    const float* bboxes = (const float*)d_in[1];  // [16,64,4]
    const float* Wm     = (const float*)d_in[2];  // [256,128]
    const float* bias   = (const float*)d_in[3];  // [256]
    float* out = (float*)d_out;                   // [16,64,256]

    __half* zh;  cudaGetSymbolAddress((void**)&zh,   g_zh);
    float* part; cudaGetSymbolAddress((void**)&part, g_part);

    dim3 tgrid(HW_ / (32 * TP_TILES), C_ / 32, B_);   // (32, 4, 16) = 2048 blocks
    transpose_kernel<<<tgrid, dim3(32, 8)>>>(z, zh);

    roi_align_kernel<<<dim3(NROI, RA_SPLIT), 32 * RA_WARPS>>>(zh, bboxes, part);

    gemm_kernel<<<NROI / ROIS_PB, OUT_>>>(part, Wm, bias, out);
}